// round 10
// baseline (speedup 1.0000x reference)
#include <cuda_runtime.h>
#include <cuda_bf16.h>
#include <cuda_fp16.h>
#include <cstdint>
#include <math.h>

// ===========================================================================
// Net_6983616823390 — binarized MLP (sm_103)
//  L1 : fp16 HMMA K=3072 + exact fp32 fixup (TAU=0.05)
//  L2-4: DUAL-PIPE hybrid — K_t=1024 bf16 HMMA (tensor) + K_p=1024 popcount
//        (ALU), same-warp fragment-mapped, exact integer merge.
//  L5 : fp32 SIMT
// ===========================================================================

#define B_ROWS 8192
#define HDIM   2000
#define HPAD   2048
#define DIN    3072
#define KT     1024          // tensor K
#define NPW    32            // pop words (K_p = 1024)

#define RED_BLOCKS 512
#define RED_THREADS 256
#define GPARTS 1024
#define APAD 40
#define CAPN (1u << 21)
#define TAU  0.05f

#define RS 80
// hybrid smem layout (bytes)
#define HYB_AS   0
#define HYB_BS   20480
#define HYB_BA   40960
#define HYB_BW   57856
#define HYB_SMR  74752
#define HYB_TOT  76800

__device__ float  d_scales[8];
__device__ double d_partials[8][GPARTS];
__device__ double d_corr;
__device__ unsigned d_flagcnt;
__device__ uint32_t d_rec_mn[CAPN];
__device__ float    d_rec_h[CAPN];

__device__ __align__(16) __half g_xh [(size_t)B_ROWS * DIN];
__device__ __align__(16) __half g_w1h[(size_t)HPAD * DIN];
__device__ __align__(16) __nv_bfloat16 g_sw2[(size_t)HPAD * HPAD];
__device__ __align__(16) __nv_bfloat16 g_sw3[(size_t)HPAD * HPAD];
__device__ __align__(16) __nv_bfloat16 g_sw4[(size_t)HPAD * HPAD];
__device__ __align__(16) uint32_t g_wb2[(size_t)HPAD * 64];
__device__ __align__(16) uint32_t g_wb3[(size_t)HPAD * 64];
__device__ __align__(16) uint32_t g_wb4[(size_t)HPAD * 64];
__device__ __align__(16) __nv_bfloat16 g_stepA[(size_t)B_ROWS * HPAD];
__device__ __align__(16) __nv_bfloat16 g_stepB[(size_t)B_ROWS * HPAD];
__device__ __align__(16) uint32_t g_bA[(size_t)B_ROWS * 64];
__device__ __align__(16) uint32_t g_bB[(size_t)B_ROWS * 64];
__device__ __align__(16) float g_h4[(size_t)B_ROWS * HDIM];

__device__ __forceinline__ uint32_t smem_u32(const void* p) {
    uint32_t a;
    asm("{ .reg .u64 t; cvta.to.shared.u64 t, %1; cvt.u32.u64 %0, t; }" : "=r"(a) : "l"(p));
    return a;
}
__device__ __forceinline__ void ldm_x4(uint32_t* r, uint32_t addr) {
    asm volatile("ldmatrix.sync.aligned.m8n8.x4.shared.b16 {%0,%1,%2,%3}, [%4];"
        : "=r"(r[0]), "=r"(r[1]), "=r"(r[2]), "=r"(r[3]) : "r"(addr));
}
__device__ __forceinline__ void mma_bf16(float* c, const uint32_t* a,
                                         uint32_t b0, uint32_t b1) {
    asm volatile(
        "mma.sync.aligned.m16n8k16.row.col.f32.bf16.bf16.f32 "
        "{%0,%1,%2,%3}, {%4,%5,%6,%7}, {%8,%9}, {%0,%1,%2,%3};"
        : "+f"(c[0]), "+f"(c[1]), "+f"(c[2]), "+f"(c[3])
        : "r"(a[0]), "r"(a[1]), "r"(a[2]), "r"(a[3]), "r"(b0), "r"(b1));
}
__device__ __forceinline__ void mma_f16(float* c, const uint32_t* a,
                                        uint32_t b0, uint32_t b1) {
    asm volatile(
        "mma.sync.aligned.m16n8k16.row.col.f32.f16.f16.f32 "
        "{%0,%1,%2,%3}, {%4,%5,%6,%7}, {%8,%9}, {%0,%1,%2,%3};"
        : "+f"(c[0]), "+f"(c[1]), "+f"(c[2]), "+f"(c[3])
        : "r"(a[0]), "r"(a[1]), "r"(a[2]), "r"(a[3]), "r"(b0), "r"(b1));
}

// ===========================================================================
// Deterministic reductions
// ===========================================================================
__global__ void __launch_bounds__(RED_THREADS)
reduce_abs_partial(const float* __restrict__ src, long n, int slot) {
    double s = 0.0;
    long stride = (long)gridDim.x * blockDim.x;
    for (long i = (long)blockIdx.x * blockDim.x + threadIdx.x; i < n; i += stride)
        s += (double)fabsf(src[i]);
    __shared__ double sm[RED_THREADS];
    sm[threadIdx.x] = s; __syncthreads();
    for (int o = RED_THREADS / 2; o > 0; o >>= 1) {
        if (threadIdx.x < o) sm[threadIdx.x] += sm[threadIdx.x + o];
        __syncthreads();
    }
    if (threadIdx.x == 0) d_partials[slot][blockIdx.x] = sm[0];
}
__global__ void __launch_bounds__(512)
reduce_finalize(int slot, double invn, int nparts, int addcorr) {
    __shared__ double sm[512];
    int t = threadIdx.x;
    double v = (t < nparts) ? d_partials[slot][t] : 0.0;
    if (t + 512 < nparts) v += d_partials[slot][t + 512];
    sm[t] = v; __syncthreads();
    for (int o = 256; o > 0; o >>= 1) {
        if (t < o) sm[t] += sm[t + o];
        __syncthreads();
    }
    if (t == 0) {
        double s = sm[0];
        if (addcorr) s += d_corr;
        d_scales[slot] = (float)(s * invn);
    }
}

// ===========================================================================
// Merged prep: x->fp16, sign(W1)->fp16, counters init  (one launch)
// ===========================================================================
#define NBX 24576   // B_ROWS*DIN/4/256
#define NBW 12288   // HPAD*DIN/2/256
__global__ void __launch_bounds__(256)
k_prep1(const float* __restrict__ x, const float* __restrict__ W1) {
    const int b = blockIdx.x;
    if (b == 0 && threadIdx.x == 0) { d_flagcnt = 0u; d_corr = 0.0; }
    if (b < NBX) {
        long gid = (long)b * 256 + threadIdx.x;
        const float4 v = *(const float4*)&x[gid * 4];
        *(__half2*)&g_xh[gid * 4]     = __floats2half2_rn(v.x, v.y);
        *(__half2*)&g_xh[gid * 4 + 2] = __floats2half2_rn(v.z, v.w);
    } else {
        long gid = (long)(b - NBX) * 256 + threadIdx.x;
        int r = (int)(gid / (DIN / 2));
        int c = (int)(gid % (DIN / 2)) * 2;
        uint32_t w = 0;
        if (r < HDIM) {
            float a = W1[(size_t)r * DIN + c], bb = W1[(size_t)r * DIN + c + 1];
            uint32_t lo = (a > 0.f) ? 0x3C00u : ((a < 0.f) ? 0xBC00u : 0u);
            uint32_t hi = (bb > 0.f) ? 0x3C00u : ((bb < 0.f) ? 0xBC00u : 0u);
            w = lo | (hi << 16);
        }
        *(uint32_t*)&g_w1h[(size_t)r * DIN + c] = w;
    }
}

__device__ __forceinline__ uint32_t sgn_pair_bf(float a, float b) {
    uint32_t lo = (a > 0.f) ? 0x3F80u : ((a < 0.f) ? 0xBF80u : 0u);
    uint32_t hi = (b > 0.f) ? 0x3F80u : ((b < 0.f) ? 0xBF80u : 0u);
    return lo | (hi << 16);
}
__global__ void __launch_bounds__(256)
k_sign_w(const float* __restrict__ W, __nv_bfloat16* __restrict__ dst) {
    long gid = (long)blockIdx.x * blockDim.x + threadIdx.x;
    long n2 = (long)HPAD * HPAD / 2;
    if (gid >= n2) return;
    int r = (int)(gid / (HPAD / 2));
    int c = (int)(gid % (HPAD / 2)) * 2;
    uint32_t w = 0;
    if (r < HDIM && c < HDIM)
        w = sgn_pair_bf(W[(size_t)r * HDIM + c], W[(size_t)r * HDIM + c + 1]);
    *(uint32_t*)&dst[(size_t)r * HPAD + c] = w;
}
// pack W rows into (w>0) bitmasks, 64 words/row (warp per row)
__global__ void __launch_bounds__(256)
k_pack_w(const float* __restrict__ W, uint32_t* __restrict__ wp) {
    int warp = (blockIdx.x * blockDim.x + threadIdx.x) >> 5;
    int lane = threadIdx.x & 31;
    if (warp >= HPAD) return;
    for (int kw = 0; kw < 64; kw++) {
        int k = kw * 32 + lane;
        float v = (warp < HDIM && k < HDIM) ? W[(size_t)warp * HDIM + k] : 0.f;
        uint32_t bal = __ballot_sync(0xffffffffu, v > 0.f);
        if (lane == 0) wp[(size_t)warp * 64 + kw] = bal;
    }
}

// ===========================================================================
// L1: fp16 HMMA, K=3072 — emits bf16 steps (n<KT), packed bits, flags, mean
// ===========================================================================
__global__ void __launch_bounds__(256, 2)
gemm_l1(const __half* __restrict__ A, const __half* __restrict__ Bw,
        const float* __restrict__ bias, __nv_bfloat16* __restrict__ stepOut,
        uint8_t* __restrict__ bitsOut)
{
    __shared__ __align__(16) char As[2][128 * APAD * 2];
    __shared__ __align__(16) char Bs[2][128 * APAD * 2];
    __shared__ double smr[256];

    const int tid  = threadIdx.x;
    const int wid  = tid >> 5;
    const int lane = tid & 31;
    const int wm   = wid >> 2;
    const int wn   = wid & 3;
    const int brow = blockIdx.y * 128;
    const int bcol = blockIdx.x * 128;
    const int NC   = DIN / 32;

    const int lrow = tid >> 2;
    const int lseg = tid & 3;
    const __half* Abase = A  + (size_t)(brow + lrow) * DIN + lseg * 8;
    const __half* Bbase = Bw + (size_t)(bcol + lrow) * DIN + lseg * 8;
    const size_t step64 = (size_t)64 * DIN;
    const uint32_t RSB = APAD * 2;
    const uint32_t st_off = lrow * RSB + lseg * 16;
    const uint32_t as0 = smem_u32(&As[0][0]);
    const uint32_t bs0 = smem_u32(&Bs[0][0]);
    const uint32_t BUFB = 128 * RSB;

    const int aj = lane & 7, asel = lane >> 3;
    const uint32_t a_off = (uint32_t)((wm * 64 + aj + (asel & 1) * 8) * RSB + (asel >> 1) * 16);
    const uint32_t b_off = (uint32_t)((wn * 32 + aj + (asel >> 1) * 8) * RSB + (asel & 1) * 16);

    float acc[4][4][4];
#pragma unroll
    for (int i = 0; i < 4; i++)
#pragma unroll
        for (int j = 0; j < 4; j++)
#pragma unroll
            for (int q = 0; q < 4; q++) acc[i][j][q] = 0.f;

    {
        uint4 a0 = *(const uint4*)Abase;
        uint4 a1 = *(const uint4*)(Abase + step64);
        uint4 b0 = *(const uint4*)Bbase;
        uint4 b1 = *(const uint4*)(Bbase + step64);
        *(uint4*)(As[0] + st_off) = a0;
        *(uint4*)(As[0] + st_off + 64 * RSB) = a1;
        *(uint4*)(Bs[0] + st_off) = b0;
        *(uint4*)(Bs[0] + st_off + 64 * RSB) = b1;
    }
    __syncthreads();

    for (int it = 0; it < NC; it++) {
        const int buf = it & 1;
        uint4 pa0, pa1, pb0, pb1;
        const bool more = (it + 1 < NC);
        if (more) {
            const __half* An = Abase + (size_t)(it + 1) * 32;
            const __half* Bn = Bbase + (size_t)(it + 1) * 32;
            pa0 = *(const uint4*)An;
            pa1 = *(const uint4*)(An + step64);
            pb0 = *(const uint4*)Bn;
            pb1 = *(const uint4*)(Bn + step64);
        }
        const uint32_t ab = as0 + buf * BUFB;
        const uint32_t bb = bs0 + buf * BUFB;
#pragma unroll
        for (int ks = 0; ks < 2; ks++) {
            uint32_t bfr[2][4];
#pragma unroll
            for (int p = 0; p < 2; p++)
                ldm_x4(bfr[p], bb + b_off + p * 16 * RSB + ks * 32);
#pragma unroll
            for (int mf = 0; mf < 4; mf++) {
                uint32_t afr[4];
                ldm_x4(afr, ab + a_off + mf * 16 * RSB + ks * 32);
#pragma unroll
                for (int nf = 0; nf < 4; nf++)
                    mma_f16(acc[mf][nf], afr,
                            bfr[nf >> 1][(nf & 1) * 2], bfr[nf >> 1][(nf & 1) * 2 + 1]);
            }
        }
        if (more) {
            char* ad = As[buf ^ 1] + st_off;
            char* bd = Bs[buf ^ 1] + st_off;
            *(uint4*)ad = pa0;
            *(uint4*)(ad + 64 * RSB) = pa1;
            *(uint4*)bd = pb0;
            *(uint4*)(bd + 64 * RSB) = pb1;
        }
        __syncthreads();
    }

    const float alpha = d_scales[0];
    const float athr  = alpha * TAU;
    double mysum = 0.0;
#pragma unroll
    for (int mf = 0; mf < 4; mf++) {
        const int m0 = brow + wm * 64 + mf * 16 + (lane >> 2);
#pragma unroll
        for (int nf = 0; nf < 4; nf++) {
            const int n0 = bcol + wn * 32 + nf * 8;
            const int n  = n0 + 2 * (lane & 3);
            const bool v0 = (n < HDIM), v1 = (n + 1 < HDIM);
            const float bv0 = v0 ? bias[n] : 0.f;
            const float bv1 = v1 ? bias[n + 1] : 0.f;
            float p00 = fmaf(alpha, acc[mf][nf][0], bv0);
            float p01 = fmaf(alpha, acc[mf][nf][1], bv1);
            float p10 = fmaf(alpha, acc[mf][nf][2], bv0);
            float p11 = fmaf(alpha, acc[mf][nf][3], bv1);
            float h00 = (v0 && p00 > 0.f) ? p00 : 0.f;
            float h01 = (v1 && p01 > 0.f) ? p01 : 0.f;
            float h10 = (v0 && p10 > 0.f) ? p10 : 0.f;
            float h11 = (v1 && p11 > 0.f) ? p11 : 0.f;
            mysum += (double)h00 + (double)h01 + (double)h10 + (double)h11;
            if (n < KT) {
                uint32_t s0 = (h00 > 0.f ? 0x3F80u : 0u) | ((h01 > 0.f ? 0x3F80u : 0u) << 16);
                uint32_t s1 = (h10 > 0.f ? 0x3F80u : 0u) | ((h11 > 0.f ? 0x3F80u : 0u) << 16);
                *(uint32_t*)&stepOut[(size_t)m0 * HPAD + n] = s0;
                *(uint32_t*)&stepOut[(size_t)(m0 + 8) * HPAD + n] = s1;
            }
            // packed bits (byte per 8 cols via shfl compose)
            uint32_t v = (h00 > 0.f ? 1u : 0u) | (h01 > 0.f ? 2u : 0u)
                       | (((h10 > 0.f ? 1u : 0u) | (h11 > 0.f ? 2u : 0u)) << 8);
            v |= __shfl_xor_sync(0xffffffffu, v, 1) << 2;
            v |= __shfl_xor_sync(0xffffffffu, v, 2) << 4;
            if ((lane & 3) == 0) {
                bitsOut[(size_t)m0 * 256 + (n0 >> 3)]       = (uint8_t)(v & 0xFF);
                bitsOut[(size_t)(m0 + 8) * 256 + (n0 >> 3)] = (uint8_t)((v >> 8) & 0xFF);
            }
#define FLAGCHK(p, h, mm, nn, vv)                                               \
            if ((vv) && fabsf(p) < athr) {                                      \
                unsigned id = atomicAdd(&d_flagcnt, 1u);                        \
                if (id < CAPN) {                                                \
                    d_rec_mn[id] = ((uint32_t)(mm) << 11) | (uint32_t)(nn);     \
                    d_rec_h[id] = (h);                                          \
                }                                                               \
            }
            FLAGCHK(p00, h00, m0,     n,     v0)
            FLAGCHK(p01, h01, m0,     n + 1, v1)
            FLAGCHK(p10, h10, m0 + 8, n,     v0)
            FLAGCHK(p11, h11, m0 + 8, n + 1, v1)
#undef FLAGCHK
        }
    }

    smr[tid] = mysum;
    __syncthreads();
    for (int o = 128; o > 0; o >>= 1) {
        if (tid < o) smr[tid] += smr[tid + o];
        __syncthreads();
    }
    if (tid == 0)
        d_partials[4][blockIdx.y * gridDim.x + blockIdx.x] = smr[0];
}

// ===========================================================================
// Exact fp32 fixup of flagged L1 outputs: bf16 step + bit + mean correction
// ===========================================================================
__global__ void __launch_bounds__(256)
k_fixup(const float* __restrict__ x, const float* __restrict__ b1,
        __nv_bfloat16* __restrict__ stepOut, uint32_t* __restrict__ bitsOut)
{
    const int lane = threadIdx.x & 31;
    const unsigned gw = (blockIdx.x * blockDim.x + threadIdx.x) >> 5;
    const unsigned nw = (gridDim.x * blockDim.x) >> 5;
    unsigned cnt = d_flagcnt;
    if (cnt > CAPN) cnt = CAPN;
    const float alpha = d_scales[0];
    for (unsigned i = gw; i < cnt; i += nw) {
        uint32_t mn = d_rec_mn[i];
        int m = (int)(mn >> 11), n = (int)(mn & 2047u);
        const float* xr = x + (size_t)m * DIN;
        const __half* wr = g_w1h + (size_t)n * DIN;
        float s = 0.f;
        for (int k = lane; k < DIN; k += 32)
            s = fmaf(xr[k], __half2float(wr[k]), s);
#pragma unroll
        for (int o = 16; o > 0; o >>= 1)
            s += __shfl_xor_sync(0xffffffffu, s, o);
        if (lane == 0) {
            float p = fmaf(alpha, s, b1[n]);
            float hn = (p > 0.f) ? p : 0.f;
            if (n < KT)
                ((uint16_t*)stepOut)[(size_t)m * HPAD + n] = (hn > 0.f) ? 0x3F80u : 0u;
            uint32_t* wp = bitsOut + (size_t)m * 64 + (n >> 5);
            if (hn > 0.f) atomicOr(wp, 1u << (n & 31));
            else          atomicAnd(wp, ~(1u << (n & 31)));
            atomicAdd(&d_corr, (double)hn - (double)d_rec_h[i]);
        }
    }
}

// ===========================================================================
// L2-4 HYBRID: C = HMMA(bf16 steps, k<1024) + popcount(bits, k in [1024,2048))
// ===========================================================================
__global__ void __launch_bounds__(256, 1)
gemm_hyb(const __nv_bfloat16* __restrict__ A, const uint32_t* __restrict__ Abits,
         const __nv_bfloat16* __restrict__ Bw, const uint32_t* __restrict__ Wbits,
         const float* __restrict__ bias,
         __nv_bfloat16* __restrict__ stepOut, uint8_t* __restrict__ bitsOut,
         float* __restrict__ h4Out, int sA, int sW, int slot)
{
    extern __shared__ char smem[];
    uint32_t* sbA = (uint32_t*)(smem + HYB_BA);
    uint32_t* sbW = (uint32_t*)(smem + HYB_BW);
    double* smr = (double*)(smem + HYB_SMR);

    const int tid  = threadIdx.x;
    const int wid  = tid >> 5;
    const int lane = tid & 31;
    const int wm   = wid >> 2;
    const int wn   = wid & 3;
    const int brow = blockIdx.y * 128;
    const int bcol = blockIdx.x * 128;
    const int NC   = KT / 32;   // 32

    const int lrow = tid >> 2;
    const int lseg = tid & 3;
    const __nv_bfloat16* Abase = A  + (size_t)(brow + lrow) * HPAD + lseg * 8;
    const __nv_bfloat16* Bbase = Bw + (size_t)(bcol + lrow) * HPAD + lseg * 8;
    const size_t step64 = (size_t)64 * HPAD;
    const uint32_t RSB = 80;
    const uint32_t st_off = lrow * RSB + lseg * 16;
    const uint32_t as0 = smem_u32(smem + HYB_AS);
    const uint32_t bs0 = smem_u32(smem + HYB_BS);
    const uint32_t BUFB = 128 * RSB;

    const int aj = lane & 7, asel = lane >> 3;
    const uint32_t a_off = (uint32_t)((wm * 64 + aj + (asel & 1) * 8) * RSB + (asel >> 1) * 16);
    const uint32_t b_off = (uint32_t)((wn * 32 + aj + (asel >> 1) * 8) * RSB + (asel & 1) * 16);

    // pop-part smem row indices (stride 33 words)
    int prow[8], pcol[8];
#pragma unroll
    for (int i = 0; i < 8; i++)
        prow[i] = (wm * 64 + (i >> 1) * 16 + (i & 1) * 8 + (lane >> 2)) * 33;
#pragma unroll
    for (int j = 0; j < 8; j++)
        pcol[j] = (wn * 32 + (j >> 1) * 8 + (j & 1) + 2 * (lane & 3)) * 33;

    float acc[4][4][4];
    int accP[8][8];
    int pa[8];
#pragma unroll
    for (int i = 0; i < 4; i++)
#pragma unroll
        for (int j = 0; j < 4; j++)
#pragma unroll
            for (int q = 0; q < 4; q++) acc[i][j][q] = 0.f;
#pragma unroll
    for (int i = 0; i < 8; i++) {
        pa[i] = 0;
#pragma unroll
        for (int j = 0; j < 8; j++) accP[i][j] = 0;
    }

    // load bit tiles (once) + tensor stage 0
    for (int idx = tid; idx < 128 * NPW; idx += 256) {
        int r = idx >> 5, w = idx & 31;
        sbA[r * 33 + w] = Abits[(size_t)(brow + r) * 64 + 32 + w];
        sbW[r * 33 + w] = Wbits[(size_t)(bcol + r) * 64 + 32 + w];
    }
    {
        uint4 a0 = *(const uint4*)Abase;
        uint4 a1 = *(const uint4*)(Abase + step64);
        uint4 b0 = *(const uint4*)Bbase;
        uint4 b1 = *(const uint4*)(Bbase + step64);
        *(uint4*)(smem + HYB_AS + st_off) = a0;
        *(uint4*)(smem + HYB_AS + st_off + 64 * RSB) = a1;
        *(uint4*)(smem + HYB_BS + st_off) = b0;
        *(uint4*)(smem + HYB_BS + st_off + 64 * RSB) = b1;
    }
    __syncthreads();

    for (int it = 0; it < NC; it++) {
        const int buf = it & 1;
        uint4 qa0, qa1, qb0, qb1;
        const bool more = (it + 1 < NC);
        if (more) {
            const __nv_bfloat16* An = Abase + (size_t)(it + 1) * 32;
            const __nv_bfloat16* Bn = Bbase + (size_t)(it + 1) * 32;
            qa0 = *(const uint4*)An;
            qa1 = *(const uint4*)(An + step64);
            qb0 = *(const uint4*)Bn;
            qb1 = *(const uint4*)(Bn + step64);
        }
        const uint32_t ab = as0 + buf * BUFB;
        const uint32_t bb = bs0 + buf * BUFB;
#pragma unroll
        for (int ks = 0; ks < 2; ks++) {
            uint32_t bfr[2][4];
#pragma unroll
            for (int p = 0; p < 2; p++)
                ldm_x4(bfr[p], bb + b_off + p * 16 * RSB + ks * 32);
#pragma unroll
            for (int mf = 0; mf < 4; mf++) {
                uint32_t afr[4];
                ldm_x4(afr, ab + a_off + mf * 16 * RSB + ks * 32);
#pragma unroll
                for (int nf = 0; nf < 4; nf++)
                    mma_bf16(acc[mf][nf], afr,
                             bfr[nf >> 1][(nf & 1) * 2], bfr[nf >> 1][(nf & 1) * 2 + 1]);
            }
        }
        // popcount word `it` on the ALU pipe (fills tensor-shadow issue slots)
        {
            uint32_t aw[8], ww[8];
#pragma unroll
            for (int i = 0; i < 8; i++) aw[i] = sbA[prow[i] + it];
#pragma unroll
            for (int j = 0; j < 8; j++) ww[j] = sbW[pcol[j] + it];
#pragma unroll
            for (int i = 0; i < 8; i++) {
                pa[i] += __popc(aw[i]);
#pragma unroll
                for (int j = 0; j < 8; j++)
                    accP[i][j] += __popc(aw[i] & ww[j]);
            }
        }
        if (more) {
            char* ad = smem + HYB_AS + (buf ^ 1) * BUFB + st_off;
            char* bd = smem + HYB_BS + (buf ^ 1) * BUFB + st_off;
            *(uint4*)ad = qa0;
            *(uint4*)(ad + 64 * RSB) = qa1;
            *(uint4*)bd = qb0;
            *(uint4*)(bd + 64 * RSB) = qb1;
        }
        __syncthreads();
    }

    const float alpha = d_scales[sW] * d_scales[sA];
    double mysum = 0.0;
#pragma unroll
    for (int mf = 0; mf < 4; mf++) {
        const int m0 = brow + wm * 64 + mf * 16 + (lane >> 2);
        const int i0 = mf * 2, i1 = mf * 2 + 1;
#pragma unroll
        for (int nf = 0; nf < 4; nf++) {
            const int n0 = bcol + wn * 32 + nf * 8;
            const int n  = n0 + 2 * (lane & 3);
            const int j0 = nf * 2, j1 = nf * 2 + 1;
            const bool v0 = (n < HDIM), v1 = (n + 1 < HDIM);
            const float bv0 = v0 ? bias[n] : 0.f;
            const float bv1 = v1 ? bias[n + 1] : 0.f;
            float t00 = acc[mf][nf][0] + (float)(2 * accP[i0][j0] - pa[i0]);
            float t01 = acc[mf][nf][1] + (float)(2 * accP[i0][j1] - pa[i0]);
            float t10 = acc[mf][nf][2] + (float)(2 * accP[i1][j0] - pa[i1]);
            float t11 = acc[mf][nf][3] + (float)(2 * accP[i1][j1] - pa[i1]);
            float p00 = fmaf(alpha, t00, bv0);
            float p01 = fmaf(alpha, t01, bv1);
            float p10 = fmaf(alpha, t10, bv0);
            float p11 = fmaf(alpha, t11, bv1);
            float h00 = (v0 && p00 > 0.f) ? p00 : 0.f;
            float h01 = (v1 && p01 > 0.f) ? p01 : 0.f;
            float h10 = (v0 && p10 > 0.f) ? p10 : 0.f;
            float h11 = (v1 && p11 > 0.f) ? p11 : 0.f;
            mysum += (double)h00 + (double)h01 + (double)h10 + (double)h11;
            if (stepOut && n < KT) {
                uint32_t s0 = (h00 > 0.f ? 0x3F80u : 0u) | ((h01 > 0.f ? 0x3F80u : 0u) << 16);
                uint32_t s1 = (h10 > 0.f ? 0x3F80u : 0u) | ((h11 > 0.f ? 0x3F80u : 0u) << 16);
                *(uint32_t*)&stepOut[(size_t)m0 * HPAD + n] = s0;
                *(uint32_t*)&stepOut[(size_t)(m0 + 8) * HPAD + n] = s1;
            }
            if (bitsOut) {
                uint32_t v = (h00 > 0.f ? 1u : 0u) | (h01 > 0.f ? 2u : 0u)
                           | (((h10 > 0.f ? 1u : 0u) | (h11 > 0.f ? 2u : 0u)) << 8);
                v |= __shfl_xor_sync(0xffffffffu, v, 1) << 2;
                v |= __shfl_xor_sync(0xffffffffu, v, 2) << 4;
                if ((lane & 3) == 0) {
                    bitsOut[(size_t)m0 * 256 + (n0 >> 3)]       = (uint8_t)(v & 0xFF);
                    bitsOut[(size_t)(m0 + 8) * 256 + (n0 >> 3)] = (uint8_t)((v >> 8) & 0xFF);
                }
            }
            if (h4Out && v0) {
                *(float2*)&h4Out[(size_t)m0 * HDIM + n] = make_float2(h00, h01);
                *(float2*)&h4Out[(size_t)(m0 + 8) * HDIM + n] = make_float2(h10, h11);
            }
        }
    }
    smr[tid] = mysum;
    __syncthreads();
    for (int o = 128; o > 0; o >>= 1) {
        if (tid < o) smr[tid] += smr[tid + o];
        __syncthreads();
    }
    if (tid == 0 && slot >= 0)
        d_partials[slot][blockIdx.y * gridDim.x + blockIdx.x] = smr[0];
}

// ===========================================================================
// Final fp32 layer (N=10)
// ===========================================================================
__global__ void __launch_bounds__(256)
fc_out(const float* __restrict__ H4, const float* __restrict__ W5,
       const float* __restrict__ b5, float* __restrict__ out)
{
    int warp = (blockIdx.x * blockDim.x + threadIdx.x) >> 5;
    int lane = threadIdx.x & 31;
    if (warp >= B_ROWS) return;
    const float* h = H4 + (long)warp * HDIM;
    float acc[10];
#pragma unroll
    for (int j = 0; j < 10; j++) acc[j] = 0.f;
    for (int k = lane; k < HDIM; k += 32) {
        float hv = h[k];
#pragma unroll
        for (int j = 0; j < 10; j++)
            acc[j] = fmaf(hv, W5[j * HDIM + k], acc[j]);
    }
#pragma unroll
    for (int j = 0; j < 10; j++)
#pragma unroll
        for (int o = 16; o > 0; o >>= 1)
            acc[j] += __shfl_down_sync(0xffffffffu, acc[j], o);
    if (lane == 0)
#pragma unroll
        for (int j = 0; j < 10; j++)
            out[(long)warp * 10 + j] = acc[j] + b5[j];
}

// ===========================================================================
extern "C" void kernel_launch(void* const* d_in, const int* in_sizes, int n_in,
                              void* d_out, int out_size)
{
    const float* x  = (const float*)d_in[0];
    const float* W1 = (const float*)d_in[1];
    const float* b1 = (const float*)d_in[2];
    const float* W2 = (const float*)d_in[3];
    const float* b2 = (const float*)d_in[4];
    const float* W3 = (const float*)d_in[5];
    const float* b3 = (const float*)d_in[6];
    const float* W4 = (const float*)d_in[7];
    const float* b4 = (const float*)d_in[8];
    const float* W5 = (const float*)d_in[9];
    const float* b5 = (const float*)d_in[10];
    float* out = (float*)d_out;

    __half *xh, *w1h;
    __nv_bfloat16 *sw2, *sw3, *sw4, *stA, *stB;
    uint32_t *wb2, *wb3, *wb4, *bA, *bB;
    float* h4;
    cudaGetSymbolAddress((void**)&xh,  g_xh);
    cudaGetSymbolAddress((void**)&w1h, g_w1h);
    cudaGetSymbolAddress((void**)&sw2, g_sw2);
    cudaGetSymbolAddress((void**)&sw3, g_sw3);
    cudaGetSymbolAddress((void**)&sw4, g_sw4);
    cudaGetSymbolAddress((void**)&wb2, g_wb2);
    cudaGetSymbolAddress((void**)&wb3, g_wb3);
    cudaGetSymbolAddress((void**)&wb4, g_wb4);
    cudaGetSymbolAddress((void**)&stA, g_stepA);
    cudaGetSymbolAddress((void**)&stB, g_stepB);
    cudaGetSymbolAddress((void**)&bA,  g_bA);
    cudaGetSymbolAddress((void**)&bB,  g_bB);
    cudaGetSymbolAddress((void**)&h4,  g_h4);

    cudaFuncSetAttribute(gemm_hyb, cudaFuncAttributeMaxDynamicSharedMemorySize, HYB_TOT);

    const long nW1 = (long)HDIM * DIN;
    const long nW  = (long)HDIM * HDIM;
    const double invH = 1.0 / ((double)B_ROWS * HDIM);

    dim3 grid(HPAD / 128, B_ROWS / 128);   // (16, 64) = 1024 CTAs

    k_prep1<<<NBX + NBW, 256>>>(x, W1);                                      // 1
    reduce_abs_partial<<<RED_BLOCKS, RED_THREADS>>>(W1, nW1, 0);             // 2
    reduce_finalize<<<1, 512>>>(0, 1.0 / (double)nW1, RED_BLOCKS, 0);        // 3
    gemm_l1<<<grid, 256>>>(xh, w1h, b1, stA, (uint8_t*)bA);                  // 4 (profiled)
    k_fixup<<<512, 256>>>(x, b1, stA, bA);                                   // 5
    reduce_finalize<<<1, 512>>>(4, invH, GPARTS, 1);                         // 6

    reduce_abs_partial<<<RED_BLOCKS, RED_THREADS>>>(W2, nW, 1);
    reduce_finalize<<<1, 512>>>(1, 1.0 / (double)nW, RED_BLOCKS, 0);
    reduce_abs_partial<<<RED_BLOCKS, RED_THREADS>>>(W3, nW, 2);
    reduce_finalize<<<1, 512>>>(2, 1.0 / (double)nW, RED_BLOCKS, 0);
    reduce_abs_partial<<<RED_BLOCKS, RED_THREADS>>>(W4, nW, 3);
    reduce_finalize<<<1, 512>>>(3, 1.0 / (double)nW, RED_BLOCKS, 0);
    k_sign_w<<<(int)(((long)HPAD * HPAD / 2 + 255) / 256), 256>>>(W2, sw2);
    k_sign_w<<<(int)(((long)HPAD * HPAD / 2 + 255) / 256), 256>>>(W3, sw3);
    k_sign_w<<<(int)(((long)HPAD * HPAD / 2 + 255) / 256), 256>>>(W4, sw4);
    k_pack_w<<<HPAD / 8, 256>>>(W2, wb2);
    k_pack_w<<<HPAD / 8, 256>>>(W3, wb3);
    k_pack_w<<<HPAD / 8, 256>>>(W4, wb4);

    gemm_hyb<<<grid, 256, HYB_TOT>>>(stA, bA, sw2, wb2, b2,
                                     stB, (uint8_t*)bB, nullptr, 4, 1, 5);
    reduce_finalize<<<1, 512>>>(5, invH, GPARTS, 0);
    gemm_hyb<<<grid, 256, HYB_TOT>>>(stB, bB, sw3, wb3, b3,
                                     stA, (uint8_t*)bA, nullptr, 5, 2, 6);
    reduce_finalize<<<1, 512>>>(6, invH, GPARTS, 0);
    gemm_hyb<<<grid, 256, HYB_TOT>>>(stA, bA, sw4, wb4, b4,
                                     nullptr, nullptr, h4, 6, 3, -1);

    fc_out<<<(B_ROWS * 32) / 256, 256>>>(h4, W5, b5, out);

    (void)in_sizes; (void)n_in; (void)out_size;
}

// round 11
// speedup vs baseline: 1.8264x; 1.8264x over previous
#include <cuda_runtime.h>
#include <cuda_bf16.h>
#include <cuda_fp16.h>
#include <cstdint>
#include <math.h>

// ===========================================================================
// Net_6983616823390 — binarized MLP (sm_103)
//  L1 : fp16 HMMA K=3072 + exact fp32 fixup (TAU=0.05)
//  L2-4: CTA-specialized hybrid — CTAs bx<8: bf16 HMMA (cols 0-1023, smem
//        pipe); CTAs bx>=8: bit-packed popcount (cols 1024-2047, ALU pipe).
//        Both exact integer math over full K=2048.
//  bit packing: standalone ballot kernel (12us) — NOT in GEMM epilogues.
//  L5 : fp32 SIMT
// ===========================================================================

#define B_ROWS 8192
#define HDIM   2000
#define HPAD   2048
#define DIN    3072
#define KW     64
#define KWP    65

#define RED_BLOCKS 512
#define RED_THREADS 256
#define GPARTS 1024
#define APAD 40
#define CAPN (1u << 21)
#define TAU  0.05f

// hybrid dynamic smem layout (bytes)
#define T_AS   0                    // tensor: As[2] @ 0, 10240
#define T_BS   20480                // tensor: Bs[2] @ 20480, 30720
#define P_A    0                    // pop: A bits 128*65*4 = 33280
#define P_W    33280                // pop: W bits
#define SMR_OFF 66560
#define HYB_TOT 68608

__device__ float  d_scales[8];
__device__ double d_partials[8][GPARTS];
__device__ double d_corr;
__device__ unsigned d_flagcnt;
__device__ uint32_t d_rec_mn[CAPN];
__device__ float    d_rec_h[CAPN];

__device__ __align__(16) __half g_xh [(size_t)B_ROWS * DIN];
__device__ __align__(16) __half g_w1h[(size_t)HPAD * DIN];
__device__ __align__(16) __nv_bfloat16 g_sw2[(size_t)HPAD * HPAD];
__device__ __align__(16) __nv_bfloat16 g_sw3[(size_t)HPAD * HPAD];
__device__ __align__(16) __nv_bfloat16 g_sw4[(size_t)HPAD * HPAD];
__device__ __align__(16) uint32_t g_wb2[(size_t)HPAD * KW];
__device__ __align__(16) uint32_t g_wb3[(size_t)HPAD * KW];
__device__ __align__(16) uint32_t g_wb4[(size_t)HPAD * KW];
__device__ __align__(16) __nv_bfloat16 g_stepA[(size_t)B_ROWS * HPAD];
__device__ __align__(16) __nv_bfloat16 g_stepB[(size_t)B_ROWS * HPAD];
__device__ __align__(16) uint32_t g_bA[(size_t)B_ROWS * KW];
__device__ __align__(16) uint32_t g_bB[(size_t)B_ROWS * KW];
__device__ __align__(16) float g_h4[(size_t)B_ROWS * HDIM];

__device__ __forceinline__ uint32_t smem_u32(const void* p) {
    uint32_t a;
    asm("{ .reg .u64 t; cvta.to.shared.u64 t, %1; cvt.u32.u64 %0, t; }" : "=r"(a) : "l"(p));
    return a;
}
__device__ __forceinline__ void ldm_x4(uint32_t* r, uint32_t addr) {
    asm volatile("ldmatrix.sync.aligned.m8n8.x4.shared.b16 {%0,%1,%2,%3}, [%4];"
        : "=r"(r[0]), "=r"(r[1]), "=r"(r[2]), "=r"(r[3]) : "r"(addr));
}
__device__ __forceinline__ void mma_bf16(float* c, const uint32_t* a,
                                         uint32_t b0, uint32_t b1) {
    asm volatile(
        "mma.sync.aligned.m16n8k16.row.col.f32.bf16.bf16.f32 "
        "{%0,%1,%2,%3}, {%4,%5,%6,%7}, {%8,%9}, {%0,%1,%2,%3};"
        : "+f"(c[0]), "+f"(c[1]), "+f"(c[2]), "+f"(c[3])
        : "r"(a[0]), "r"(a[1]), "r"(a[2]), "r"(a[3]), "r"(b0), "r"(b1));
}
__device__ __forceinline__ void mma_f16(float* c, const uint32_t* a,
                                        uint32_t b0, uint32_t b1) {
    asm volatile(
        "mma.sync.aligned.m16n8k16.row.col.f32.f16.f16.f32 "
        "{%0,%1,%2,%3}, {%4,%5,%6,%7}, {%8,%9}, {%0,%1,%2,%3};"
        : "+f"(c[0]), "+f"(c[1]), "+f"(c[2]), "+f"(c[3])
        : "r"(a[0]), "r"(a[1]), "r"(a[2]), "r"(a[3]), "r"(b0), "r"(b1));
}

// ===========================================================================
// Deterministic reductions
// ===========================================================================
__global__ void __launch_bounds__(RED_THREADS)
reduce_abs_partial(const float* __restrict__ src, long n, int slot) {
    double s = 0.0;
    long stride = (long)gridDim.x * blockDim.x;
    for (long i = (long)blockIdx.x * blockDim.x + threadIdx.x; i < n; i += stride)
        s += (double)fabsf(src[i]);
    __shared__ double sm[RED_THREADS];
    sm[threadIdx.x] = s; __syncthreads();
    for (int o = RED_THREADS / 2; o > 0; o >>= 1) {
        if (threadIdx.x < o) sm[threadIdx.x] += sm[threadIdx.x + o];
        __syncthreads();
    }
    if (threadIdx.x == 0) d_partials[slot][blockIdx.x] = sm[0];
}
__global__ void __launch_bounds__(512)
reduce_finalize(int slot, double invn, int nparts, int addcorr) {
    __shared__ double sm[512];
    int t = threadIdx.x;
    double v = (t < nparts) ? d_partials[slot][t] : 0.0;
    if (t + 512 < nparts) v += d_partials[slot][t + 512];
    sm[t] = v; __syncthreads();
    for (int o = 256; o > 0; o >>= 1) {
        if (t < o) sm[t] += sm[t + o];
        __syncthreads();
    }
    if (t == 0) {
        double s = sm[0];
        if (addcorr) s += d_corr;
        d_scales[slot] = (float)(s * invn);
    }
}

// ===========================================================================
// Prep kernels
// ===========================================================================
#define NBX 24576
#define NBW 12288
__global__ void __launch_bounds__(256)
k_prep1(const float* __restrict__ x, const float* __restrict__ W1) {
    const int b = blockIdx.x;
    if (b == 0 && threadIdx.x == 0) { d_flagcnt = 0u; d_corr = 0.0; }
    if (b < NBX) {
        long gid = (long)b * 256 + threadIdx.x;
        const float4 v = *(const float4*)&x[gid * 4];
        *(__half2*)&g_xh[gid * 4]     = __floats2half2_rn(v.x, v.y);
        *(__half2*)&g_xh[gid * 4 + 2] = __floats2half2_rn(v.z, v.w);
    } else {
        long gid = (long)(b - NBX) * 256 + threadIdx.x;
        int r = (int)(gid / (DIN / 2));
        int c = (int)(gid % (DIN / 2)) * 2;
        uint32_t w = 0;
        if (r < HDIM) {
            float a = W1[(size_t)r * DIN + c], bb = W1[(size_t)r * DIN + c + 1];
            uint32_t lo = (a > 0.f) ? 0x3C00u : ((a < 0.f) ? 0xBC00u : 0u);
            uint32_t hi = (bb > 0.f) ? 0x3C00u : ((bb < 0.f) ? 0xBC00u : 0u);
            w = lo | (hi << 16);
        }
        *(uint32_t*)&g_w1h[(size_t)r * DIN + c] = w;
    }
}
__device__ __forceinline__ uint32_t sgn_pair_bf(float a, float b) {
    uint32_t lo = (a > 0.f) ? 0x3F80u : ((a < 0.f) ? 0xBF80u : 0u);
    uint32_t hi = (b > 0.f) ? 0x3F80u : ((b < 0.f) ? 0xBF80u : 0u);
    return lo | (hi << 16);
}
__global__ void __launch_bounds__(256)
k_sign_w(const float* __restrict__ W, __nv_bfloat16* __restrict__ dst) {
    long gid = (long)blockIdx.x * blockDim.x + threadIdx.x;
    long n2 = (long)HPAD * HPAD / 2;
    if (gid >= n2) return;
    int r = (int)(gid / (HPAD / 2));
    int c = (int)(gid % (HPAD / 2)) * 2;
    uint32_t w = 0;
    if (r < HDIM && c < HDIM)
        w = sgn_pair_bf(W[(size_t)r * HDIM + c], W[(size_t)r * HDIM + c + 1]);
    *(uint32_t*)&dst[(size_t)r * HPAD + c] = w;
}
__global__ void __launch_bounds__(256)
k_pack_w(const float* __restrict__ W, uint32_t* __restrict__ wp) {
    int warp = (blockIdx.x * blockDim.x + threadIdx.x) >> 5;
    int lane = threadIdx.x & 31;
    if (warp >= HPAD) return;
    for (int kw = 0; kw < KW; kw++) {
        int k = kw * 32 + lane;
        float v = (warp < HDIM && k < HDIM) ? W[(size_t)warp * HDIM + k] : 0.f;
        uint32_t bal = __ballot_sync(0xffffffffu, v > 0.f);
        if (lane == 0) wp[(size_t)warp * KW + kw] = bal;
    }
}
// pack bf16 steps -> bits (ballot over nonzero), warp per row
__global__ void __launch_bounds__(256)
k_pack_a(const __nv_bfloat16* __restrict__ steps, uint32_t* __restrict__ bits) {
    int warp = (blockIdx.x * blockDim.x + threadIdx.x) >> 5;
    int lane = threadIdx.x & 31;
    if (warp >= B_ROWS) return;
    const uint16_t* row = (const uint16_t*)steps + (size_t)warp * HPAD;
#pragma unroll 4
    for (int kw = 0; kw < KW; kw++) {
        uint16_t v = row[kw * 32 + lane];
        uint32_t bal = __ballot_sync(0xffffffffu, v != 0);
        if (lane == 0) bits[(size_t)warp * KW + kw] = bal;
    }
}

// ===========================================================================
// L1: fp16 HMMA, K=3072 (round-9 form: steps + flags + mean, no bit packing)
// ===========================================================================
__global__ void __launch_bounds__(256, 2)
gemm_l1(const __half* __restrict__ A, const __half* __restrict__ Bw,
        const float* __restrict__ bias, __nv_bfloat16* __restrict__ stepOut)
{
    __shared__ __align__(16) char As[2][128 * APAD * 2];
    __shared__ __align__(16) char Bs[2][128 * APAD * 2];
    __shared__ double smr[256];

    const int tid  = threadIdx.x;
    const int wid  = tid >> 5;
    const int lane = tid & 31;
    const int wm   = wid >> 2;
    const int wn   = wid & 3;
    const int brow = blockIdx.y * 128;
    const int bcol = blockIdx.x * 128;
    const int NC   = DIN / 32;

    const int lrow = tid >> 2;
    const int lseg = tid & 3;
    const __half* Abase = A  + (size_t)(brow + lrow) * DIN + lseg * 8;
    const __half* Bbase = Bw + (size_t)(bcol + lrow) * DIN + lseg * 8;
    const size_t step64 = (size_t)64 * DIN;
    const uint32_t RSB = APAD * 2;
    const uint32_t st_off = lrow * RSB + lseg * 16;
    const uint32_t as0 = smem_u32(&As[0][0]);
    const uint32_t bs0 = smem_u32(&Bs[0][0]);
    const uint32_t BUFB = 128 * RSB;

    const int aj = lane & 7, asel = lane >> 3;
    const uint32_t a_off = (uint32_t)((wm * 64 + aj + (asel & 1) * 8) * RSB + (asel >> 1) * 16);
    const uint32_t b_off = (uint32_t)((wn * 32 + aj + (asel >> 1) * 8) * RSB + (asel & 1) * 16);

    float acc[4][4][4];
#pragma unroll
    for (int i = 0; i < 4; i++)
#pragma unroll
        for (int j = 0; j < 4; j++)
#pragma unroll
            for (int q = 0; q < 4; q++) acc[i][j][q] = 0.f;

    {
        uint4 a0 = *(const uint4*)Abase;
        uint4 a1 = *(const uint4*)(Abase + step64);
        uint4 b0 = *(const uint4*)Bbase;
        uint4 b1 = *(const uint4*)(Bbase + step64);
        *(uint4*)(As[0] + st_off) = a0;
        *(uint4*)(As[0] + st_off + 64 * RSB) = a1;
        *(uint4*)(Bs[0] + st_off) = b0;
        *(uint4*)(Bs[0] + st_off + 64 * RSB) = b1;
    }
    __syncthreads();

    for (int it = 0; it < NC; it++) {
        const int buf = it & 1;
        uint4 pa0, pa1, pb0, pb1;
        const bool more = (it + 1 < NC);
        if (more) {
            const __half* An = Abase + (size_t)(it + 1) * 32;
            const __half* Bn = Bbase + (size_t)(it + 1) * 32;
            pa0 = *(const uint4*)An;
            pa1 = *(const uint4*)(An + step64);
            pb0 = *(const uint4*)Bn;
            pb1 = *(const uint4*)(Bn + step64);
        }
        const uint32_t ab = as0 + buf * BUFB;
        const uint32_t bb = bs0 + buf * BUFB;
#pragma unroll
        for (int ks = 0; ks < 2; ks++) {
            uint32_t bfr[2][4];
#pragma unroll
            for (int p = 0; p < 2; p++)
                ldm_x4(bfr[p], bb + b_off + p * 16 * RSB + ks * 32);
#pragma unroll
            for (int mf = 0; mf < 4; mf++) {
                uint32_t afr[4];
                ldm_x4(afr, ab + a_off + mf * 16 * RSB + ks * 32);
#pragma unroll
                for (int nf = 0; nf < 4; nf++)
                    mma_f16(acc[mf][nf], afr,
                            bfr[nf >> 1][(nf & 1) * 2], bfr[nf >> 1][(nf & 1) * 2 + 1]);
            }
        }
        if (more) {
            char* ad = As[buf ^ 1] + st_off;
            char* bd = Bs[buf ^ 1] + st_off;
            *(uint4*)ad = pa0;
            *(uint4*)(ad + 64 * RSB) = pa1;
            *(uint4*)bd = pb0;
            *(uint4*)(bd + 64 * RSB) = pb1;
        }
        __syncthreads();
    }

    const float alpha = d_scales[0];
    const float athr  = alpha * TAU;
    double mysum = 0.0;
#pragma unroll
    for (int mf = 0; mf < 4; mf++) {
        const int m0 = brow + wm * 64 + mf * 16 + (lane >> 2);
#pragma unroll
        for (int nf = 0; nf < 4; nf++) {
            const int n = bcol + wn * 32 + nf * 8 + 2 * (lane & 3);
            const bool v0 = (n < HDIM), v1 = (n + 1 < HDIM);
            const float bv0 = v0 ? bias[n] : 0.f;
            const float bv1 = v1 ? bias[n + 1] : 0.f;
            float p00 = fmaf(alpha, acc[mf][nf][0], bv0);
            float p01 = fmaf(alpha, acc[mf][nf][1], bv1);
            float p10 = fmaf(alpha, acc[mf][nf][2], bv0);
            float p11 = fmaf(alpha, acc[mf][nf][3], bv1);
            float h00 = (v0 && p00 > 0.f) ? p00 : 0.f;
            float h01 = (v1 && p01 > 0.f) ? p01 : 0.f;
            float h10 = (v0 && p10 > 0.f) ? p10 : 0.f;
            float h11 = (v1 && p11 > 0.f) ? p11 : 0.f;
            mysum += (double)h00 + (double)h01 + (double)h10 + (double)h11;
            uint32_t s0 = (h00 > 0.f ? 0x3F80u : 0u) | ((h01 > 0.f ? 0x3F80u : 0u) << 16);
            uint32_t s1 = (h10 > 0.f ? 0x3F80u : 0u) | ((h11 > 0.f ? 0x3F80u : 0u) << 16);
            *(uint32_t*)&stepOut[(size_t)m0 * HPAD + n] = s0;
            *(uint32_t*)&stepOut[(size_t)(m0 + 8) * HPAD + n] = s1;
#define FLAGCHK(p, h, mm, nn, vv)                                               \
            if ((vv) && fabsf(p) < athr) {                                      \
                unsigned id = atomicAdd(&d_flagcnt, 1u);                        \
                if (id < CAPN) {                                                \
                    d_rec_mn[id] = ((uint32_t)(mm) << 11) | (uint32_t)(nn);     \
                    d_rec_h[id] = (h);                                          \
                }                                                               \
            }
            FLAGCHK(p00, h00, m0,     n,     v0)
            FLAGCHK(p01, h01, m0,     n + 1, v1)
            FLAGCHK(p10, h10, m0 + 8, n,     v0)
            FLAGCHK(p11, h11, m0 + 8, n + 1, v1)
#undef FLAGCHK
        }
    }

    smr[tid] = mysum;
    __syncthreads();
    for (int o = 128; o > 0; o >>= 1) {
        if (tid < o) smr[tid] += smr[tid + o];
        __syncthreads();
    }
    if (tid == 0)
        d_partials[4][blockIdx.y * gridDim.x + blockIdx.x] = smr[0];
}

// ===========================================================================
// Exact fp32 fixup of flagged L1 outputs (runs BEFORE k_pack_a)
// ===========================================================================
__global__ void __launch_bounds__(256)
k_fixup(const float* __restrict__ x, const float* __restrict__ b1,
        __nv_bfloat16* __restrict__ stepOut)
{
    const int lane = threadIdx.x & 31;
    const unsigned gw = (blockIdx.x * blockDim.x + threadIdx.x) >> 5;
    const unsigned nw = (gridDim.x * blockDim.x) >> 5;
    unsigned cnt = d_flagcnt;
    if (cnt > CAPN) cnt = CAPN;
    const float alpha = d_scales[0];
    for (unsigned i = gw; i < cnt; i += nw) {
        uint32_t mn = d_rec_mn[i];
        int m = (int)(mn >> 11), n = (int)(mn & 2047u);
        const float* xr = x + (size_t)m * DIN;
        const __half* wr = g_w1h + (size_t)n * DIN;
        float s = 0.f;
        for (int k = lane; k < DIN; k += 32)
            s = fmaf(xr[k], __half2float(wr[k]), s);
#pragma unroll
        for (int o = 16; o > 0; o >>= 1)
            s += __shfl_xor_sync(0xffffffffu, s, o);
        if (lane == 0) {
            float p = fmaf(alpha, s, b1[n]);
            float hn = (p > 0.f) ? p : 0.f;
            ((uint16_t*)stepOut)[(size_t)m * HPAD + n] = (hn > 0.f) ? 0x3F80u : 0u;
            atomicAdd(&d_corr, (double)hn - (double)d_rec_h[i]);
        }
    }
}

// ===========================================================================
// L2-4 CTA-specialized hybrid.
//  bx<8 : bf16 HMMA on cols [0,1024)       (smem pipe)
//  bx>=8: popcount on cols [1024,2048)     (ALU pipe)
// ===========================================================================
__global__ void __launch_bounds__(256, 2)
gemm_hyb(const __nv_bfloat16* __restrict__ A, const uint32_t* __restrict__ Abits,
         const __nv_bfloat16* __restrict__ Bw, const uint32_t* __restrict__ Wbits,
         const float* __restrict__ bias,
         __nv_bfloat16* __restrict__ stepOut, float* __restrict__ h4Out,
         int sA, int sW, int slot)
{
    extern __shared__ char smem[];
    double* smr = (double*)(smem + SMR_OFF);
    const int tid  = threadIdx.x;
    const int brow = blockIdx.y * 128;
    const int bcol = blockIdx.x * 128;
    const float alpha = d_scales[sW] * d_scales[sA];
    double mysum = 0.0;

    if (blockIdx.x < 8) {
        // ================= tensor mode =================
        const int wid  = tid >> 5;
        const int lane = tid & 31;
        const int wm   = wid >> 2;
        const int wn   = wid & 3;
        const int NC   = HPAD / 32;   // 64

        const int lrow = tid >> 2;
        const int lseg = tid & 3;
        const __nv_bfloat16* Abase = A  + (size_t)(brow + lrow) * HPAD + lseg * 8;
        const __nv_bfloat16* Bbase = Bw + (size_t)(bcol + lrow) * HPAD + lseg * 8;
        const size_t step64 = (size_t)64 * HPAD;
        const uint32_t RSB = 80;
        const uint32_t st_off = lrow * RSB + lseg * 16;
        const uint32_t as0 = smem_u32(smem + T_AS);
        const uint32_t bs0 = smem_u32(smem + T_BS);
        const uint32_t BUFB = 128 * RSB;

        const int aj = lane & 7, asel = lane >> 3;
        const uint32_t a_off = (uint32_t)((wm * 64 + aj + (asel & 1) * 8) * RSB + (asel >> 1) * 16);
        const uint32_t b_off = (uint32_t)((wn * 32 + aj + (asel >> 1) * 8) * RSB + (asel & 1) * 16);

        float acc[4][4][4];
#pragma unroll
        for (int i = 0; i < 4; i++)
#pragma unroll
            for (int j = 0; j < 4; j++)
#pragma unroll
                for (int q = 0; q < 4; q++) acc[i][j][q] = 0.f;

        {
            uint4 a0 = *(const uint4*)Abase;
            uint4 a1 = *(const uint4*)(Abase + step64);
            uint4 b0 = *(const uint4*)Bbase;
            uint4 b1 = *(const uint4*)(Bbase + step64);
            *(uint4*)(smem + T_AS + st_off) = a0;
            *(uint4*)(smem + T_AS + st_off + 64 * RSB) = a1;
            *(uint4*)(smem + T_BS + st_off) = b0;
            *(uint4*)(smem + T_BS + st_off + 64 * RSB) = b1;
        }
        __syncthreads();

        for (int it = 0; it < NC; it++) {
            const int buf = it & 1;
            uint4 pa0, pa1, pb0, pb1;
            const bool more = (it + 1 < NC);
            if (more) {
                const __nv_bfloat16* An = Abase + (size_t)(it + 1) * 32;
                const __nv_bfloat16* Bn = Bbase + (size_t)(it + 1) * 32;
                pa0 = *(const uint4*)An;
                pa1 = *(const uint4*)(An + step64);
                pb0 = *(const uint4*)Bn;
                pb1 = *(const uint4*)(Bn + step64);
            }
            const uint32_t ab = as0 + buf * BUFB;
            const uint32_t bb = bs0 + buf * BUFB;
#pragma unroll
            for (int ks = 0; ks < 2; ks++) {
                uint32_t bfr[2][4];
#pragma unroll
                for (int p = 0; p < 2; p++)
                    ldm_x4(bfr[p], bb + b_off + p * 16 * RSB + ks * 32);
#pragma unroll
                for (int mf = 0; mf < 4; mf++) {
                    uint32_t afr[4];
                    ldm_x4(afr, ab + a_off + mf * 16 * RSB + ks * 32);
#pragma unroll
                    for (int nf = 0; nf < 4; nf++)
                        mma_bf16(acc[mf][nf], afr,
                                 bfr[nf >> 1][(nf & 1) * 2], bfr[nf >> 1][(nf & 1) * 2 + 1]);
                }
            }
            if (more) {
                char* ad = smem + T_AS + (buf ^ 1) * BUFB + st_off;
                char* bd = smem + T_BS + (buf ^ 1) * BUFB + st_off;
                *(uint4*)ad = pa0;
                *(uint4*)(ad + 64 * RSB) = pa1;
                *(uint4*)bd = pb0;
                *(uint4*)(bd + 64 * RSB) = pb1;
            }
            __syncthreads();
        }

#pragma unroll
        for (int mf = 0; mf < 4; mf++) {
            const int m0 = brow + wm * 64 + mf * 16 + (lane >> 2);
#pragma unroll
            for (int nf = 0; nf < 4; nf++) {
                const int n = bcol + wn * 32 + nf * 8 + 2 * (lane & 3);   // < 1024
                const float bv0 = bias[n];
                const float bv1 = bias[n + 1];
                float p00 = fmaf(alpha, acc[mf][nf][0], bv0);
                float p01 = fmaf(alpha, acc[mf][nf][1], bv1);
                float p10 = fmaf(alpha, acc[mf][nf][2], bv0);
                float p11 = fmaf(alpha, acc[mf][nf][3], bv1);
                float h00 = (p00 > 0.f) ? p00 : 0.f;
                float h01 = (p01 > 0.f) ? p01 : 0.f;
                float h10 = (p10 > 0.f) ? p10 : 0.f;
                float h11 = (p11 > 0.f) ? p11 : 0.f;
                mysum += (double)h00 + (double)h01 + (double)h10 + (double)h11;
                if (stepOut) {
                    uint32_t s0 = (h00 > 0.f ? 0x3F80u : 0u) | ((h01 > 0.f ? 0x3F80u : 0u) << 16);
                    uint32_t s1 = (h10 > 0.f ? 0x3F80u : 0u) | ((h11 > 0.f ? 0x3F80u : 0u) << 16);
                    *(uint32_t*)&stepOut[(size_t)m0 * HPAD + n] = s0;
                    *(uint32_t*)&stepOut[(size_t)(m0 + 8) * HPAD + n] = s1;
                }
                if (h4Out) {
                    *(float2*)&h4Out[(size_t)m0 * HDIM + n] = make_float2(h00, h01);
                    *(float2*)&h4Out[(size_t)(m0 + 8) * HDIM + n] = make_float2(h10, h11);
                }
            }
        }
    } else {
        // ================= popcount mode =================
        uint32_t* sa = (uint32_t*)(smem + P_A);
        uint32_t* sw = (uint32_t*)(smem + P_W);
        const int tr = tid >> 4;        // 0..15
        const int tc = tid & 15;        // 0..15

#pragma unroll
        for (int q = 0; q < 8; q++) {
            int idx = tid + q * 256;
            int r = idx >> 4, k4 = (idx & 15) * 4;
            uint4 va = ((const uint4*)(Abits + (size_t)(brow + r) * KW))[idx & 15];
            sa[r * KWP + k4 + 0] = va.x; sa[r * KWP + k4 + 1] = va.y;
            sa[r * KWP + k4 + 2] = va.z; sa[r * KWP + k4 + 3] = va.w;
            uint4 vw = ((const uint4*)(Wbits + (size_t)(bcol + r) * KW))[idx & 15];
            sw[r * KWP + k4 + 0] = vw.x; sw[r * KWP + k4 + 1] = vw.y;
            sw[r * KWP + k4 + 2] = vw.z; sw[r * KWP + k4 + 3] = vw.w;
        }
        __syncthreads();

        int acc[8][8];
        int pa[8];
#pragma unroll
        for (int i = 0; i < 8; i++) {
            pa[i] = 0;
#pragma unroll
            for (int j = 0; j < 8; j++) acc[i][j] = 0;
        }

#pragma unroll 2
        for (int k = 0; k < KW; k++) {
            uint32_t aw[8], ww[8];
#pragma unroll
            for (int i = 0; i < 8; i++) aw[i] = sa[(tr * 8 + i) * KWP + k];
#pragma unroll
            for (int j = 0; j < 8; j++) ww[j] = sw[(tc * 8 + j) * KWP + k];
#pragma unroll
            for (int i = 0; i < 8; i++) {
                pa[i] += __popc(aw[i]);
#pragma unroll
                for (int j = 0; j < 8; j++)
                    acc[i][j] += __popc(aw[i] & ww[j]);
            }
        }

        const int n0 = bcol + tc * 8;         // 1024..2040
        const bool valid = (n0 < HDIM);
        float bv[8];
        if (valid) {
            float4 b0 = *(const float4*)&bias[n0];
            float4 b1 = *(const float4*)&bias[n0 + 4];
            bv[0]=b0.x; bv[1]=b0.y; bv[2]=b0.z; bv[3]=b0.w;
            bv[4]=b1.x; bv[5]=b1.y; bv[6]=b1.z; bv[7]=b1.w;
        } else {
#pragma unroll
            for (int j = 0; j < 8; j++) bv[j] = 0.f;
        }

#pragma unroll
        for (int i = 0; i < 8; i++) {
            const int m = brow + tr * 8 + i;
            float hv[8];
#pragma unroll
            for (int j = 0; j < 8; j++) {
                int S = 2 * acc[i][j] - pa[i];
                float p = fmaf(alpha, (float)S, bv[j]);
                float h = (valid && p > 0.f) ? p : 0.f;
                hv[j] = h;
                mysum += (double)h;
            }
            if (stepOut) {
                uint32_t pk[4];
#pragma unroll
                for (int q = 0; q < 4; q++)
                    pk[q] = (hv[2*q]   > 0.f ? 0x3F80u : 0u)
                          | ((hv[2*q+1] > 0.f ? 0x3F80u : 0u) << 16);
                *(uint4*)&stepOut[(size_t)m * HPAD + n0] =
                    make_uint4(pk[0], pk[1], pk[2], pk[3]);
            }
            if (h4Out && valid) {
                *(float4*)&h4Out[(size_t)m * HDIM + n0]     = make_float4(hv[0], hv[1], hv[2], hv[3]);
                *(float4*)&h4Out[(size_t)m * HDIM + n0 + 4] = make_float4(hv[4], hv[5], hv[6], hv[7]);
            }
        }
    }

    smr[tid] = mysum;
    __syncthreads();
    for (int o = 128; o > 0; o >>= 1) {
        if (tid < o) smr[tid] += smr[tid + o];
        __syncthreads();
    }
    if (tid == 0 && slot >= 0)
        d_partials[slot][blockIdx.y * gridDim.x + blockIdx.x] = smr[0];
}

// ===========================================================================
// Final fp32 layer (N=10)
// ===========================================================================
__global__ void __launch_bounds__(256)
fc_out(const float* __restrict__ H4, const float* __restrict__ W5,
       const float* __restrict__ b5, float* __restrict__ out)
{
    int warp = (blockIdx.x * blockDim.x + threadIdx.x) >> 5;
    int lane = threadIdx.x & 31;
    if (warp >= B_ROWS) return;
    const float* h = H4 + (long)warp * HDIM;
    float acc[10];
#pragma unroll
    for (int j = 0; j < 10; j++) acc[j] = 0.f;
    for (int k = lane; k < HDIM; k += 32) {
        float hv = h[k];
#pragma unroll
        for (int j = 0; j < 10; j++)
            acc[j] = fmaf(hv, W5[j * HDIM + k], acc[j]);
    }
#pragma unroll
    for (int j = 0; j < 10; j++)
#pragma unroll
        for (int o = 16; o > 0; o >>= 1)
            acc[j] += __shfl_down_sync(0xffffffffu, acc[j], o);
    if (lane == 0)
#pragma unroll
        for (int j = 0; j < 10; j++)
            out[(long)warp * 10 + j] = acc[j] + b5[j];
}

// ===========================================================================
extern "C" void kernel_launch(void* const* d_in, const int* in_sizes, int n_in,
                              void* d_out, int out_size)
{
    const float* x  = (const float*)d_in[0];
    const float* W1 = (const float*)d_in[1];
    const float* b1 = (const float*)d_in[2];
    const float* W2 = (const float*)d_in[3];
    const float* b2 = (const float*)d_in[4];
    const float* W3 = (const float*)d_in[5];
    const float* b3 = (const float*)d_in[6];
    const float* W4 = (const float*)d_in[7];
    const float* b4 = (const float*)d_in[8];
    const float* W5 = (const float*)d_in[9];
    const float* b5 = (const float*)d_in[10];
    float* out = (float*)d_out;

    __half *xh, *w1h;
    __nv_bfloat16 *sw2, *sw3, *sw4, *stA, *stB;
    uint32_t *wb2, *wb3, *wb4, *bA, *bB;
    float* h4;
    cudaGetSymbolAddress((void**)&xh,  g_xh);
    cudaGetSymbolAddress((void**)&w1h, g_w1h);
    cudaGetSymbolAddress((void**)&sw2, g_sw2);
    cudaGetSymbolAddress((void**)&sw3, g_sw3);
    cudaGetSymbolAddress((void**)&sw4, g_sw4);
    cudaGetSymbolAddress((void**)&wb2, g_wb2);
    cudaGetSymbolAddress((void**)&wb3, g_wb3);
    cudaGetSymbolAddress((void**)&wb4, g_wb4);
    cudaGetSymbolAddress((void**)&stA, g_stepA);
    cudaGetSymbolAddress((void**)&stB, g_stepB);
    cudaGetSymbolAddress((void**)&bA,  g_bA);
    cudaGetSymbolAddress((void**)&bB,  g_bB);
    cudaGetSymbolAddress((void**)&h4,  g_h4);

    cudaFuncSetAttribute(gemm_hyb, cudaFuncAttributeMaxDynamicSharedMemorySize, HYB_TOT);

    const long nW1 = (long)HDIM * DIN;
    const long nW  = (long)HDIM * HDIM;
    const double invH = 1.0 / ((double)B_ROWS * HDIM);

    dim3 grid(HPAD / 128, B_ROWS / 128);   // (16, 64)

    k_prep1<<<NBX + NBW, 256>>>(x, W1);
    reduce_abs_partial<<<RED_BLOCKS, RED_THREADS>>>(W1, nW1, 0);
    reduce_finalize<<<1, 512>>>(0, 1.0 / (double)nW1, RED_BLOCKS, 0);
    gemm_l1<<<grid, 256>>>(xh, w1h, b1, stA);
    k_fixup<<<512, 256>>>(x, b1, stA);
    k_pack_a<<<B_ROWS / 8, 256>>>(stA, bA);
    reduce_finalize<<<1, 512>>>(4, invH, GPARTS, 1);

    reduce_abs_partial<<<RED_BLOCKS, RED_THREADS>>>(W2, nW, 1);
    reduce_finalize<<<1, 512>>>(1, 1.0 / (double)nW, RED_BLOCKS, 0);
    reduce_abs_partial<<<RED_BLOCKS, RED_THREADS>>>(W3, nW, 2);
    reduce_finalize<<<1, 512>>>(2, 1.0 / (double)nW, RED_BLOCKS, 0);
    reduce_abs_partial<<<RED_BLOCKS, RED_THREADS>>>(W4, nW, 3);
    reduce_finalize<<<1, 512>>>(3, 1.0 / (double)nW, RED_BLOCKS, 0);
    k_sign_w<<<(int)(((long)HPAD * HPAD / 2 + 255) / 256), 256>>>(W2, sw2);
    k_sign_w<<<(int)(((long)HPAD * HPAD / 2 + 255) / 256), 256>>>(W3, sw3);
    k_sign_w<<<(int)(((long)HPAD * HPAD / 2 + 255) / 256), 256>>>(W4, sw4);
    k_pack_w<<<HPAD / 8, 256>>>(W2, wb2);
    k_pack_w<<<HPAD / 8, 256>>>(W3, wb3);
    k_pack_w<<<HPAD / 8, 256>>>(W4, wb4);

    gemm_hyb<<<grid, 256, HYB_TOT>>>(stA, bA, sw2, wb2, b2, stB, nullptr, 4, 1, 5);
    k_pack_a<<<B_ROWS / 8, 256>>>(stB, bB);
    reduce_finalize<<<1, 512>>>(5, invH, GPARTS, 0);
    gemm_hyb<<<grid, 256, HYB_TOT>>>(stB, bB, sw3, wb3, b3, stA, nullptr, 5, 2, 6);
    k_pack_a<<<B_ROWS / 8, 256>>>(stA, bA);
    reduce_finalize<<<1, 512>>>(6, invH, GPARTS, 0);
    gemm_hyb<<<grid, 256, HYB_TOT>>>(stA, bA, sw4, wb4, b4, nullptr, h4, 6, 3, -1);

    fc_out<<<(B_ROWS * 32) / 256, 256>>>(h4, W5, b5, out);

    (void)in_sizes; (void)n_in; (void)out_size;
}